// round 14
// baseline (speedup 1.0000x reference)
#include <cuda_runtime.h>
#include <cuda_bf16.h>
#include <math.h>
#include <stdint.h>
#include <stddef.h>

// Problem constants
#define BBATCH 64
#define SSEQ   2048
#define JJ     25
#define HID    256
#define OUTD   128
#define TM     128          // frames per CTA
#define NTHR   512
#define K1     272          // GEMM1 K (264 real + 8 pad)
#define CH1    17           // K1/16 chunks
#define CH2    16           // GEMM2 K chunks (256/16)
#define NCHNK  (CH1 + CH2)  // 33 unified weight chunks
#define PNS    77

// smem strides (bytes)
#define FSB 560             // feat row stride   -> banks 12 mod 32
#define HSB 528             // hidden row stride -> banks 4 mod 32

// Weight chunk sizes (pre-fragmented: [n8 group][lane 32][16B = bH0,bH1,bL0,bL1])
#define W1CHB 16384
#define W2CHB 8192

// smem layout (byte offsets)
#define MB_POSE 0
#define MB_F0   8                        // full[0..2] at 8,16,24
#define MB_C0   32                       // consumed[0..2] at 32,40,48
#define REG0    64                       // raw pose slab / weight ring slots 0,1
#define WBUF0   REG0
#define WBUF1   (REG0 + W1CHB)
#define OFF_FH  (REG0 + 39040)           // 39104
#define OFF_FL  (OFF_FH + 71680)         // 110784
#define OFF_PN  (OFF_FL + 71680)         // 182464 (pn; first 16KB reused as slot 2)
#define SMEM_TOTAL (OFF_PN + 130 * PNS * 4)   // 222504

#define POSES_BYTES ((size_t)BBATCH * SSEQ * JJ * 3 * 4)

// Pre-fragmented folded weights (written by prep each launch)
__device__ __align__(16) unsigned char g_W1F[CH1 * W1CHB];   // 278528 B
__device__ __align__(16) unsigned char g_W2F[CH2 * W2CHB];   // 131072 B
__device__ float g_b1c[HID];

__constant__ int c_conn[13][2] = {
    {0,1},{1,5},{1,6},{5,7},{7,9},{6,8},{8,10},
    {1,11},{1,12},{11,13},{13,15},{12,14},{14,16}};

// ======================= helpers ==========================================
__device__ __forceinline__ uint32_t smem_u32(const void* p) {
    uint32_t a;
    asm("{ .reg .u64 t; cvta.to.shared.u64 t, %1; cvt.u32.u64 %0, t; }" : "=r"(a) : "l"(p));
    return a;
}
#define MBAR_INIT(mb, n) asm volatile("mbarrier.init.shared.b64 [%0], %1;" :: "r"(mb), "r"(n) : "memory")
#define MBAR_EXPECT(mb, bytes) asm volatile("mbarrier.arrive.expect_tx.shared.b64 _, [%0], %1;" :: "r"(mb), "r"(bytes) : "memory")
#define MBAR_ARRIVE(mb) asm volatile("mbarrier.arrive.shared.b64 _, [%0];" :: "r"(mb) : "memory")
#define MBAR_WAIT(mb, par) do {                                              \
    uint32_t _mb = (mb), _p = (par), _d;                                     \
    asm volatile("{ .reg .pred p; mbarrier.try_wait.parity.acquire.cta.shared::cta.b64 p, [%1], %2; selp.b32 %0,1,0,p; }" \
        : "=r"(_d) : "r"(_mb), "r"(_p) : "memory");                          \
    if (!_d) {                                                               \
        asm volatile("{ .reg .pred P1; WL_%=: mbarrier.try_wait.parity.acquire.cta.shared::cta.b64 P1, [%0], %1, 0x989680;" \
            " @P1 bra.uni WD_%=; bra.uni WL_%=; WD_%=: }"                    \
            :: "r"(_mb), "r"(_p) : "memory");                                \
    } } while (0)

__device__ __forceinline__ void bulk_g2s(uint32_t dst, const void* gsrc, uint32_t bytes, uint32_t mb) {
    uint64_t g = (uint64_t)__cvta_generic_to_global(gsrc);
    asm volatile("cp.async.bulk.shared::cluster.global.mbarrier::complete_tx::bytes [%0], [%1], %2, [%3];"
        :: "r"(dst), "l"(g), "r"(bytes), "r"(mb) : "memory");
}

__device__ __forceinline__ void ldm_x4(uint32_t* r, uint32_t saddr) {
    asm volatile("ldmatrix.sync.aligned.m8n8.x4.shared.b16 {%0,%1,%2,%3}, [%4];"
        : "=r"(r[0]), "=r"(r[1]), "=r"(r[2]), "=r"(r[3]) : "r"(saddr));
}

// HMMA m16n8k16 row.col f32.bf16.bf16.f32, D accumulates in place.
__device__ __forceinline__ void mma16816(float* d, const uint32_t* a, uint32_t b0, uint32_t b1) {
    asm volatile(
        "mma.sync.aligned.m16n8k16.row.col.f32.bf16.bf16.f32 "
        "{%0,%1,%2,%3}, {%4,%5,%6,%7}, {%8,%9}, {%0,%1,%2,%3};"
        : "+f"(d[0]), "+f"(d[1]), "+f"(d[2]), "+f"(d[3])
        : "r"(a[0]), "r"(a[1]), "r"(a[2]), "r"(a[3]), "r"(b0), "r"(b1));
}

__device__ __forceinline__ void splitpack(float f0, float f1, uint32_t& hi, uint32_t& lo) {
    __nv_bfloat16 h0 = __float2bfloat16(f0);
    __nv_bfloat16 h1 = __float2bfloat16(f1);
    __nv_bfloat16 l0 = __float2bfloat16(f0 - __bfloat162float(h0));
    __nv_bfloat16 l1 = __float2bfloat16(f1 - __bfloat162float(h1));
    hi = (uint32_t)__bfloat16_as_ushort(h0) | ((uint32_t)__bfloat16_as_ushort(h1) << 16);
    lo = (uint32_t)__bfloat16_as_ushort(l0) | ((uint32_t)__bfloat16_as_ushort(l1) << 16);
}

// Unified weight-chunk stream: 0..16 = W1 chunks, 17..32 = W2 chunks
__device__ __forceinline__ const void* chunk_src(int i) {
    return (i < CH1) ? (const void*)(g_W1F + (size_t)i * W1CHB)
                     : (const void*)(g_W2F + (size_t)(i - CH1) * W2CHB);
}
__device__ __forceinline__ uint32_t chunk_bytes(int i) {
    return (i < CH1) ? W1CHB : W2CHB;
}

// ======================= prep: fold + split + fragment weights =============
__global__ void prep_kernel(const float* __restrict__ W1, const float* __restrict__ b1,
                            const float* __restrict__ gamma, const float* __restrict__ beta,
                            const float* __restrict__ mean, const float* __restrict__ var,
                            const float* __restrict__ jw, const float* __restrict__ W2) {
    int t = threadIdx.x, blk = blockIdx.x;
    if (blk < K1) {
        int k = blk, h = t;          // t in [0,256)
        float g = gamma[h] * rsqrtf(var[h] + 1e-5f);
        float w = 0.0f;
        if (k < 264) {
            int korig, jidx;
            if (k < 225) { int sect = k / 75; int r = k % 75; jidx = r / 3; korig = jidx * 12 + sect * 3 + r % 3; }
            else         { int a = k - 225; jidx = a / 3; korig = jidx * 12 + 9 + a % 3; }
            w = W1[korig * HID + h] * g * jw[jidx];
        }
        __nv_bfloat16 hi = __float2bfloat16(w);
        __nv_bfloat16 lo = __float2bfloat16(w - __bfloat162float(hi));
        int chunk = k >> 4, kc = k & 15, n8 = h >> 3, qr = h & 7;
        int lane = qr * 4 + ((kc & 7) >> 1);
        int boff = (kc >> 3) * 4 + (kc & 1) * 2;
        size_t idx = (((size_t)chunk * 32 + n8) * 32 + lane) * 16 + boff;
        *(__nv_bfloat16*)(g_W1F + idx)     = hi;
        *(__nv_bfloat16*)(g_W1F + idx + 8) = lo;
        if (k == 0) g_b1c[h] = (b1[h] - mean[h]) * g + beta[h];
    } else if (t < 128) {
        int k = blk - K1, n = t;     // k in [0,256)
        float w = W2[k * OUTD + n];
        __nv_bfloat16 hi = __float2bfloat16(w);
        __nv_bfloat16 lo = __float2bfloat16(w - __bfloat162float(hi));
        int chunk = k >> 4, kc = k & 15, n8 = n >> 3, qr = n & 7;
        int lane = qr * 4 + ((kc & 7) >> 1);
        int boff = (kc >> 3) * 4 + (kc & 1) * 2;
        size_t idx = (((size_t)chunk * 16 + n8) * 32 + lane) * 16 + boff;
        *(__nv_bfloat16*)(g_W2F + idx)     = hi;
        *(__nv_bfloat16*)(g_W2F + idx + 8) = lo;
    }
}

// ======================= feature value ====================================
__device__ __forceinline__ float featval(int k, const float* P, const float* Pm1,
                                         const float* Pm2, bool has1, bool has2) {
    if (k < 75) return P[k];
    if (k < 150) { int i = k - 75; return has1 ? (P[i] - Pm1[i]) : 0.0f; }
    if (k < 225) {
        int i = k - 150;
        if (!has1) return 0.0f;
        float v = P[i] - Pm1[i];
        float vm1 = has2 ? (Pm1[i] - Pm2[i]) : 0.0f;
        return v - vm1;
    }
    if (k < 264) {
        int a = k - 225, c = a / 3, d = a % 3;
        int i0 = c_conn[c][0] * 3, i1 = c_conn[c][1] * 3;
        float vx = P[i1] - P[i0], vy = P[i1 + 1] - P[i0 + 1], vz = P[i1 + 2] - P[i0 + 2];
        float n = fmaxf(sqrtf(vx * vx + vy * vy + vz * vz), 1e-12f);
        float comp = (d == 0 ? vx : (d == 1 ? vy : vz)) / n;
        return acosf(fminf(fmaxf(comp, -1.0f), 1.0f));
    }
    return 0.0f;
}

// ======================= fused HMMA kernel =================================
__global__ void __launch_bounds__(NTHR, 1)
fused_kernel(const float* __restrict__ poses, const float* __restrict__ b2,
             float* __restrict__ out) {
    extern __shared__ char smem[];
    const uint32_t sb = smem_u32(smem);
    float* pn = (float*)(smem + OFF_PN);

    const int tid  = threadIdx.x;
    const int lane = tid & 31;
    const int wid  = tid >> 5;

    const int rowbase = blockIdx.x * TM;
    const int s0 = (blockIdx.x & 15) * TM;
    const int b  = blockIdx.x >> 4;

    // ring slot smem bases
    const uint32_t wslot0 = sb + WBUF0;
    const uint32_t wslot1 = sb + WBUF1;
    const uint32_t wslot2 = sb + OFF_PN;       // reuses pn after stage 2

    // ---- init barriers + bulk-load pose slab into REG0 ----
    const int s_start = (s0 >= 2) ? (s0 - 2) : 0;
    const int nrows = 130 - (s0 == 0 ? 2 : 0);
    size_t base_bytes = ((size_t)b * SSEQ + s_start) * 300;
    size_t aligned = base_bytes & ~(size_t)15;
    const int delta = (int)(base_bytes - aligned);
    if (tid == 0) {
        MBAR_INIT(sb + MB_POSE, 1);
        #pragma unroll
        for (int s = 0; s < 3; s++) {
            MBAR_INIT(sb + MB_F0 + s * 8, 1);
            MBAR_INIT(sb + MB_C0 + s * 8, 16);
        }
        size_t want = (size_t)((nrows * 300 + delta + 15) & ~15);
        size_t avail = POSES_BYTES - aligned;             // clamp: never read OOB
        uint32_t csz = (uint32_t)(want <= avail ? want : (avail & ~(size_t)15));
        MBAR_EXPECT(sb + MB_POSE, csz);
        bulk_g2s(sb + REG0, (const char*)poses + aligned, csz, sb + MB_POSE);
    }
    __syncthreads();
    MBAR_WAIT(sb + MB_POSE, 0);

    // ---- Stage 1: normalize 130 frames (128 + 2 halo) from smem slab ----
    if (tid < 130) {
        int s = s0 - 2 + tid;
        float* dst = pn + tid * PNS;
        if (s < 0) {
            for (int i = 0; i < 75; i++) dst[i] = 0.0f;
        } else {
            const float* src = (const float*)(smem + REG0) + (delta >> 2) + (s - s_start) * 75;
            float rx = src[0], ry = src[1], rz = src[2];
            float mx = 0.0f;
            for (int j = 0; j < JJ; j++) {
                float dx = src[j*3+0] - rx, dy = src[j*3+1] - ry, dz = src[j*3+2] - rz;
                dst[j*3+0] = dx; dst[j*3+1] = dy; dst[j*3+2] = dz;
                mx = fmaxf(mx, sqrtf(dx*dx + dy*dy + dz*dz));
            }
            float inv = 1.0f / (mx + 1e-8f);
            for (int i = 0; i < 75; i++) dst[i] *= inv;
        }
    }
    __syncthreads();   // raw slab dead; slots 0,1 may now be filled

    // ---- kick weight chunks 0 & 1 (slots 0,1) — overlap with stage 2 ----
    if (tid == 0) {
        MBAR_EXPECT(sb + MB_F0 + 0, W1CHB);
        bulk_g2s(wslot0, g_W1F, W1CHB, sb + MB_F0 + 0);
        MBAR_EXPECT(sb + MB_F0 + 8, W1CHB);
        bulk_g2s(wslot1, g_W1F + W1CHB, W1CHB, sb + MB_F0 + 8);
    }

    // ---- Stage 2: features -> bf16 hi/lo smem planes ----
    {
        const int m  = tid >> 2;
        const int g4 = tid & 3;
        const float* P   = pn + (m + 2) * PNS;
        const float* Pm1 = pn + (m + 1) * PNS;
        const float* Pm2 = pn + (m + 0) * PNS;
        const bool has1 = (s0 + m) >= 1, has2 = (s0 + m) >= 2;
        char* rowH = smem + OFF_FH + (size_t)m * FSB;
        char* rowL = smem + OFF_FL + (size_t)m * FSB;
        for (int j = 0; j < 34; j++) {
            int k = g4 * 68 + 2 * j;
            float f0 = featval(k,     P, Pm1, Pm2, has1, has2);
            float f1 = featval(k + 1, P, Pm1, Pm2, has1, has2);
            uint32_t H, L;
            splitpack(f0, f1, H, L);
            *(uint32_t*)(rowH + k * 2) = H;
            *(uint32_t*)(rowL + k * 2) = L;
        }
    }
    __syncthreads();   // pn dead; slot 2 may now be filled

    // ---- kick chunk 2 into slot 2 ----
    if (tid == 0) {
        MBAR_EXPECT(sb + MB_F0 + 16, W1CHB);
        bulk_g2s(wslot2, g_W1F + 2 * (size_t)W1CHB, W1CHB, sb + MB_F0 + 16);
    }

    // ---- warp / lane geometry ----
    const int wm = wid >> 2;             // 0..3 -> m0 = wm*32
    const int wn = wid & 3;              // 0..3
    const int m0 = wm * 32;
    const int n0 = wn * 64;              // GEMM1 n-base
    const int qr = lane >> 2;
    const int qk = (lane & 3) * 2;

    // ldmatrix lane address components
    const int lrow = ((lane >> 3) & 1) * 8 + (lane & 7);
    const int lkof = (lane >> 4) * 8;

    // ======== GEMM1: hidden[128][256] = feat[128][272] @ W1c ========
    float acc[2][8][4];
    #pragma unroll
    for (int g = 0; g < 2; g++)
        #pragma unroll
        for (int nt = 0; nt < 8; nt++)
            #pragma unroll
            for (int q = 0; q < 4; q++) acc[g][nt][q] = 0.0f;

    for (int ck = 0; ck < CH1; ck++) {
        const int slot = ck % 3;
        const int ph   = (ck / 3) & 1;
        const uint32_t wbase = (slot == 2) ? wslot2 : (slot == 1 ? wslot1 : wslot0);
        MBAR_WAIT(sb + MB_F0 + slot * 8, ph);

        // A fragments via ldmatrix.x4 (H & L planes, two m16 groups)
        uint32_t aH[2][4], aL[2][4];
        {
            uint32_t kb = (uint32_t)(ck * 16 + lkof) * 2;
            #pragma unroll
            for (int g = 0; g < 2; g++) {
                uint32_t r = (uint32_t)(m0 + g * 16 + lrow);
                ldm_x4(aH[g], sb + OFF_FH + r * FSB + kb);
                ldm_x4(aL[g], sb + OFF_FL + r * FSB + kb);
            }
        }
        #pragma unroll
        for (int nt = 0; nt < 8; nt++) {
            uint4 bv = *(const uint4*)((const char*)smem + (wbase - sb) + ((wn * 8 + nt) * 32 + lane) * 16);
            mma16816(acc[0][nt], aH[0], bv.x, bv.y);
            mma16816(acc[1][nt], aH[1], bv.x, bv.y);
            mma16816(acc[0][nt], aH[0], bv.z, bv.w);
            mma16816(acc[1][nt], aH[1], bv.z, bv.w);
            mma16816(acc[0][nt], aL[0], bv.x, bv.y);
            mma16816(acc[1][nt], aL[1], bv.x, bv.y);
        }
        if (lane == 0) MBAR_ARRIVE(sb + MB_C0 + slot * 8);   // this warp done with slot
        const int r = ck + 3;
        if (tid == 0 && r < NCHNK) {
            MBAR_WAIT(sb + MB_C0 + slot * 8, ph);            // all 16 warps done
            MBAR_EXPECT(sb + MB_F0 + slot * 8, chunk_bytes(r));
            bulk_g2s(wbase, chunk_src(r), chunk_bytes(r), sb + MB_F0 + slot * 8);
        }
    }
    __syncthreads();   // all GEMM1 feat reads done before hidden overwrite

    // ---- Epilogue 1: bias + relu + split -> hidden smem (overwrites feat) ----
    #pragma unroll
    for (int g = 0; g < 2; g++) {
        int r = m0 + g * 16 + qr;
        char* rH0 = smem + OFF_FH + (size_t)r * HSB;
        char* rL0 = smem + OFF_FL + (size_t)r * HSB;
        #pragma unroll
        for (int nt = 0; nt < 8; nt++) {
            int c = n0 + nt * 8 + qk;
            float bb0 = g_b1c[c], bb1 = g_b1c[c + 1];
            float h0 = fmaxf(acc[g][nt][0] + bb0, 0.0f);
            float h1 = fmaxf(acc[g][nt][1] + bb1, 0.0f);
            float h2 = fmaxf(acc[g][nt][2] + bb0, 0.0f);
            float h3 = fmaxf(acc[g][nt][3] + bb1, 0.0f);
            uint32_t H, L;
            splitpack(h0, h1, H, L);
            *(uint32_t*)(rH0 + c * 2) = H;
            *(uint32_t*)(rL0 + c * 2) = L;
            splitpack(h2, h3, H, L);
            *(uint32_t*)(rH0 + 8 * HSB + c * 2) = H;
            *(uint32_t*)(rL0 + 8 * HSB + c * 2) = L;
        }
    }
    __syncthreads();   // hidden visible to all warps

    // ======== GEMM2: out[128][128] = hidden[128][256] @ W2 ========
    const int n02 = wn * 32;
    float acc2[2][4][4];
    #pragma unroll
    for (int g = 0; g < 2; g++)
        #pragma unroll
        for (int nt = 0; nt < 4; nt++)
            #pragma unroll
            for (int q = 0; q < 4; q++) acc2[g][nt][q] = 0.0f;

    for (int kt = 0; kt < CH2; kt++) {
        const int ck = CH1 + kt;
        const int slot = ck % 3;
        const int ph   = (ck / 3) & 1;
        const uint32_t wbase = (slot == 2) ? wslot2 : (slot == 1 ? wslot1 : wslot0);
        MBAR_WAIT(sb + MB_F0 + slot * 8, ph);

        uint32_t aH[2][4], aL[2][4];
        {
            uint32_t kb = (uint32_t)(kt * 16 + lkof) * 2;
            #pragma unroll
            for (int g = 0; g < 2; g++) {
                uint32_t r = (uint32_t)(m0 + g * 16 + lrow);
                ldm_x4(aH[g], sb + OFF_FH + r * HSB + kb);
                ldm_x4(aL[g], sb + OFF_FL + r * HSB + kb);
            }
        }
        #pragma unroll
        for (int nt = 0; nt < 4; nt++) {
            uint4 bv = *(const uint4*)((const char*)smem + (wbase - sb) + ((wn * 4 + nt) * 32 + lane) * 16);
            mma16816(acc2[0][nt], aH[0], bv.x, bv.y);
            mma16816(acc2[1][nt], aH[1], bv.x, bv.y);
            mma16816(acc2[0][nt], aH[0], bv.z, bv.w);
            mma16816(acc2[1][nt], aH[1], bv.z, bv.w);
            mma16816(acc2[0][nt], aL[0], bv.x, bv.y);
            mma16816(acc2[1][nt], aL[1], bv.x, bv.y);
        }
        if (lane == 0) MBAR_ARRIVE(sb + MB_C0 + slot * 8);
        const int r = ck + 3;
        if (tid == 0 && r < NCHNK) {
            MBAR_WAIT(sb + MB_C0 + slot * 8, ph);
            MBAR_EXPECT(sb + MB_F0 + slot * 8, chunk_bytes(r));
            bulk_g2s(wbase, chunk_src(r), chunk_bytes(r), sb + MB_F0 + slot * 8);
        }
    }

    // ---- Epilogue 2: + b2, store ----
    #pragma unroll
    for (int g = 0; g < 2; g++) {
        int r = m0 + g * 16 + qr;
        float* o0 = out + (size_t)(rowbase + r) * OUTD;
        float* o1 = out + (size_t)(rowbase + r + 8) * OUTD;
        #pragma unroll
        for (int nt = 0; nt < 4; nt++) {
            int c = n02 + nt * 8 + qk;
            float b20 = b2[c], b21 = b2[c + 1];
            float2 v0, v1;
            v0.x = acc2[g][nt][0] + b20; v0.y = acc2[g][nt][1] + b21;
            v1.x = acc2[g][nt][2] + b20; v1.y = acc2[g][nt][3] + b21;
            *reinterpret_cast<float2*>(o0 + c) = v0;
            *reinterpret_cast<float2*>(o1 + c) = v1;
        }
    }
}

// ---------------------------------------------------------------------------
extern "C" void kernel_launch(void* const* d_in, const int* in_sizes, int n_in,
                              void* d_out, int out_size) {
    const float* poses = (const float*)d_in[0];
    const float* W1    = (const float*)d_in[1];
    const float* b1    = (const float*)d_in[2];
    const float* gamma = (const float*)d_in[3];
    const float* beta  = (const float*)d_in[4];
    const float* rmean = (const float*)d_in[5];
    const float* rvar  = (const float*)d_in[6];
    const float* W2    = (const float*)d_in[7];
    const float* b2    = (const float*)d_in[8];
    const float* jw    = (const float*)d_in[9];
    float* out = (float*)d_out;

    cudaFuncSetAttribute(fused_kernel, cudaFuncAttributeMaxDynamicSharedMemorySize,
                         SMEM_TOTAL);

    prep_kernel<<<K1 + 256, 256>>>(W1, b1, gamma, beta, rmean, rvar, jw, W2);
    fused_kernel<<<(BBATCH * SSEQ) / TM, NTHR, SMEM_TOTAL>>>(poses, b2, out);
}

// round 15
// speedup vs baseline: 1.4016x; 1.4016x over previous
#include <cuda_runtime.h>
#include <cuda_bf16.h>
#include <math.h>
#include <stdint.h>
#include <stddef.h>

// Problem constants
#define BBATCH 64
#define SSEQ   2048
#define JJ     25
#define HID    256
#define OUTD   128
#define TM     64           // frames per CTA (2 CTAs/SM)
#define NTHR   256
#define K1     272          // GEMM1 K (264 real + 8 pad)
#define CH1    17           // K1/16 chunks
#define CH2    16           // GEMM2 K chunks
#define NCHNK  (CH1 + CH2)  // 33 unified weight chunks

// smem strides (bytes)
#define FSB 560             // feat row stride   -> banks 12 mod 32
#define HSB 528             // hidden row stride -> banks 4 mod 32

// Weight chunk sizes (pre-fragmented: [n8 group][lane 32][16B = bH0,bH1,bL0,bL1])
#define W1CHB 16384
#define W2CHB 8192

// smem layout (byte offsets)
#define MB_POSE 0
#define MB_F0   8                        // full[0]@8, full[1]@16
#define REG0    64                       // pose slab (19.8KB) / weight ring slots
#define WBUF0   REG0
#define WBUF1   (REG0 + W1CHB)           // 16448
#define OFF_INV 32832                    // inv[66]
#define OFF_RX  33096
#define OFF_RY  33360
#define OFF_RZ  33624
#define OFF_FH  33888                    // featH/hiddenH 64*560 = 35840
#define OFF_FL  69728                    // featL/hiddenL
#define SMEM_TOTAL 105568

#define POSES_BYTES ((size_t)BBATCH * SSEQ * JJ * 3 * 4)

// Pre-fragmented folded weights (written by prep each launch)
__device__ __align__(16) unsigned char g_W1F[CH1 * W1CHB];
__device__ __align__(16) unsigned char g_W2F[CH2 * W2CHB];
__device__ float g_b1c[HID];

__constant__ int c_conn[13][2] = {
    {0,1},{1,5},{1,6},{5,7},{7,9},{6,8},{8,10},
    {1,11},{1,12},{11,13},{13,15},{12,14},{14,16}};

// ======================= helpers ==========================================
__device__ __forceinline__ uint32_t smem_u32(const void* p) {
    uint32_t a;
    asm("{ .reg .u64 t; cvta.to.shared.u64 t, %1; cvt.u32.u64 %0, t; }" : "=r"(a) : "l"(p));
    return a;
}
#define MBAR_INIT(mb, n) asm volatile("mbarrier.init.shared.b64 [%0], %1;" :: "r"(mb), "r"(n) : "memory")
#define MBAR_EXPECT(mb, bytes) asm volatile("mbarrier.arrive.expect_tx.shared.b64 _, [%0], %1;" :: "r"(mb), "r"(bytes) : "memory")
#define MBAR_WAIT(mb, par) do {                                              \
    uint32_t _mb = (mb), _p = (par), _d;                                     \
    asm volatile("{ .reg .pred p; mbarrier.try_wait.parity.acquire.cta.shared::cta.b64 p, [%1], %2; selp.b32 %0,1,0,p; }" \
        : "=r"(_d) : "r"(_mb), "r"(_p) : "memory");                          \
    if (!_d) {                                                               \
        asm volatile("{ .reg .pred P1; WL_%=: mbarrier.try_wait.parity.acquire.cta.shared::cta.b64 P1, [%0], %1, 0x989680;" \
            " @P1 bra.uni WD_%=; bra.uni WL_%=; WD_%=: }"                    \
            :: "r"(_mb), "r"(_p) : "memory");                                \
    } } while (0)

__device__ __forceinline__ void bulk_g2s(uint32_t dst, const void* gsrc, uint32_t bytes, uint32_t mb) {
    uint64_t g = (uint64_t)__cvta_generic_to_global(gsrc);
    asm volatile("cp.async.bulk.shared::cluster.global.mbarrier::complete_tx::bytes [%0], [%1], %2, [%3];"
        :: "r"(dst), "l"(g), "r"(bytes), "r"(mb) : "memory");
}

__device__ __forceinline__ void ldm_x4(uint32_t* r, uint32_t saddr) {
    asm volatile("ldmatrix.sync.aligned.m8n8.x4.shared.b16 {%0,%1,%2,%3}, [%4];"
        : "=r"(r[0]), "=r"(r[1]), "=r"(r[2]), "=r"(r[3]) : "r"(saddr));
}

// HMMA m16n8k16 row.col f32.bf16.bf16.f32, D accumulates in place.
__device__ __forceinline__ void mma16816(float* d, const uint32_t* a, uint32_t b0, uint32_t b1) {
    asm volatile(
        "mma.sync.aligned.m16n8k16.row.col.f32.bf16.bf16.f32 "
        "{%0,%1,%2,%3}, {%4,%5,%6,%7}, {%8,%9}, {%0,%1,%2,%3};"
        : "+f"(d[0]), "+f"(d[1]), "+f"(d[2]), "+f"(d[3])
        : "r"(a[0]), "r"(a[1]), "r"(a[2]), "r"(a[3]), "r"(b0), "r"(b1));
}

__device__ __forceinline__ void splitpack(float f0, float f1, uint32_t& hi, uint32_t& lo) {
    __nv_bfloat16 h0 = __float2bfloat16(f0);
    __nv_bfloat16 h1 = __float2bfloat16(f1);
    __nv_bfloat16 l0 = __float2bfloat16(f0 - __bfloat162float(h0));
    __nv_bfloat16 l1 = __float2bfloat16(f1 - __bfloat162float(h1));
    hi = (uint32_t)__bfloat16_as_ushort(h0) | ((uint32_t)__bfloat16_as_ushort(h1) << 16);
    lo = (uint32_t)__bfloat16_as_ushort(l0) | ((uint32_t)__bfloat16_as_ushort(l1) << 16);
}

// Unified weight-chunk stream: 0..16 = W1 chunks, 17..32 = W2 chunks
__device__ __forceinline__ const void* chunk_src(int i) {
    return (i < CH1) ? (const void*)(g_W1F + (size_t)i * W1CHB)
                     : (const void*)(g_W2F + (size_t)(i - CH1) * W2CHB);
}
__device__ __forceinline__ uint32_t chunk_bytes(int i) {
    return (i < CH1) ? W1CHB : W2CHB;
}

// ======================= prep: fold + split + fragment weights =============
__global__ void prep_kernel(const float* __restrict__ W1, const float* __restrict__ b1,
                            const float* __restrict__ gamma, const float* __restrict__ beta,
                            const float* __restrict__ mean, const float* __restrict__ var,
                            const float* __restrict__ jw, const float* __restrict__ W2) {
    int t = threadIdx.x, blk = blockIdx.x;
    if (blk < K1) {
        int k = blk, h = t;          // t in [0,256)
        float g = gamma[h] * rsqrtf(var[h] + 1e-5f);
        float w = 0.0f;
        if (k < 264) {
            int korig, jidx;
            if (k < 225) { int sect = k / 75; int r = k % 75; jidx = r / 3; korig = jidx * 12 + sect * 3 + r % 3; }
            else         { int a = k - 225; jidx = a / 3; korig = jidx * 12 + 9 + a % 3; }
            w = W1[korig * HID + h] * g * jw[jidx];
        }
        __nv_bfloat16 hi = __float2bfloat16(w);
        __nv_bfloat16 lo = __float2bfloat16(w - __bfloat162float(hi));
        int chunk = k >> 4, kc = k & 15, n8 = h >> 3, qr = h & 7;
        int lane = qr * 4 + ((kc & 7) >> 1);
        int boff = (kc >> 3) * 4 + (kc & 1) * 2;
        size_t idx = (((size_t)chunk * 32 + n8) * 32 + lane) * 16 + boff;
        *(__nv_bfloat16*)(g_W1F + idx)     = hi;
        *(__nv_bfloat16*)(g_W1F + idx + 8) = lo;
        if (k == 0) g_b1c[h] = (b1[h] - mean[h]) * g + beta[h];
    } else if (t < 128) {
        int k = blk - K1, n = t;     // k in [0,256)
        float w = W2[k * OUTD + n];
        __nv_bfloat16 hi = __float2bfloat16(w);
        __nv_bfloat16 lo = __float2bfloat16(w - __bfloat162float(hi));
        int chunk = k >> 4, kc = k & 15, n8 = n >> 3, qr = n & 7;
        int lane = qr * 4 + ((kc & 7) >> 1);
        int boff = (kc >> 3) * 4 + (kc & 1) * 2;
        size_t idx = (((size_t)chunk * 16 + n8) * 32 + lane) * 16 + boff;
        *(__nv_bfloat16*)(g_W2F + idx)     = hi;
        *(__nv_bfloat16*)(g_W2F + idx + 8) = lo;
    }
}

// ======================= fused HMMA kernel =================================
__global__ void __launch_bounds__(NTHR, 2)
fused_kernel(const float* __restrict__ poses, const float* __restrict__ b2,
             float* __restrict__ out) {
    extern __shared__ char smem[];
    const uint32_t sb = smem_u32(smem);

    const int tid  = threadIdx.x;
    const int lane = tid & 31;
    const int wid  = tid >> 5;

    const int rowbase = blockIdx.x * TM;
    const int s0 = (blockIdx.x & 31) * TM;
    const int b  = blockIdx.x >> 5;

    // ---- init barriers + bulk-load pose slab into ring region ----
    const int s_start = (s0 >= 2) ? (s0 - 2) : 0;
    const int nrows = 66 - (s0 == 0 ? 2 : 0);
    size_t base_bytes = ((size_t)b * SSEQ + s_start) * 300;
    size_t aligned = base_bytes & ~(size_t)15;
    const int delta = (int)(base_bytes - aligned);
    if (tid == 0) {
        MBAR_INIT(sb + MB_POSE, 1);
        MBAR_INIT(sb + MB_F0 + 0, 1);
        MBAR_INIT(sb + MB_F0 + 8, 1);
        size_t want = (size_t)((nrows * 300 + delta + 15) & ~15);
        size_t avail = POSES_BYTES - aligned;
        uint32_t csz = (uint32_t)(want <= avail ? want : (avail & ~(size_t)15));
        MBAR_EXPECT(sb + MB_POSE, csz);
        bulk_g2s(sb + REG0, (const char*)poses + aligned, csz, sb + MB_POSE);
    }
    __syncthreads();
    MBAR_WAIT(sb + MB_POSE, 0);

    const float* slabf = (const float*)(smem + REG0) + (delta >> 2);
    const int roff0 = (s0 == 0) ? -2 : 0;       // row offset of slot t in slab = t + roff0
    float* invv = (float*)(smem + OFF_INV);
    float* rxv  = (float*)(smem + OFF_RX);
    float* ryv  = (float*)(smem + OFF_RY);
    float* rzv  = (float*)(smem + OFF_RZ);

    // ---- Stage 1: per-frame root + inverse max-dist (66 slots: 64 + 2 halo) ----
    if (tid < 66) {
        int s = s0 - 2 + tid;
        if (s < 0) {
            invv[tid] = 0.0f; rxv[tid] = 0.0f; ryv[tid] = 0.0f; rzv[tid] = 0.0f;
        } else {
            const float* src = slabf + (tid + roff0) * 75;
            float rx = src[0], ry = src[1], rz = src[2];
            float mx = 0.0f;
            for (int j = 0; j < JJ; j++) {
                float dx = src[j*3+0] - rx, dy = src[j*3+1] - ry, dz = src[j*3+2] - rz;
                mx = fmaxf(mx, sqrtf(dx*dx + dy*dy + dz*dz));
            }
            invv[tid] = 1.0f / (mx + 1e-8f);
            rxv[tid] = rx; ryv[tid] = ry; rzv[tid] = rz;
        }
    }
    __syncthreads();

    // ---- Stage 2: features -> bf16 hi/lo smem planes (direct from raw slab) ----
    {
        const int m  = tid >> 2;            // frame 0..63
        const int g4 = tid & 3;             // k quarter (68 each)
        const int tc = m + 2;
        const bool has1 = (s0 + m) >= 1, has2 = (s0 + m) >= 2;
        const float* Rc = slabf + (tc + roff0) * 75;
        const float* R1 = slabf + ((has1 ? (tc - 1) : tc) + roff0) * 75;
        const float* R2 = slabf + ((has2 ? (tc - 2) : tc) + roff0) * 75;
        const float ic = invv[tc];
        const float i1 = has1 ? invv[tc - 1] : 0.0f;
        const float i2 = has2 ? invv[tc - 2] : 0.0f;
        const float rc[3] = {rxv[tc], ryv[tc], rzv[tc]};
        const float r1[3] = {has1 ? rxv[tc-1] : 0.0f, has1 ? ryv[tc-1] : 0.0f, has1 ? rzv[tc-1] : 0.0f};
        const float r2[3] = {has2 ? rxv[tc-2] : 0.0f, has2 ? ryv[tc-2] : 0.0f, has2 ? rzv[tc-2] : 0.0f};
        char* rowH = smem + OFF_FH + (size_t)m * FSB;
        char* rowL = smem + OFF_FL + (size_t)m * FSB;

        for (int j = 0; j < 34; j++) {
            int k0 = g4 * 68 + 2 * j;
            float fv[2];
            #pragma unroll
            for (int u = 0; u < 2; u++) {
                int k = k0 + u;
                float val = 0.0f;
                if (k < 75) {
                    int d = k % 3;
                    val = (Rc[k] - rc[d]) * ic;
                } else if (k < 150) {
                    int i = k - 75; int d = i % 3;
                    val = has1 ? ((Rc[i] - rc[d]) * ic - (R1[i] - r1[d]) * i1) : 0.0f;
                } else if (k < 225) {
                    int i = k - 150; int d = i % 3;
                    if (has1) {
                        float pc = (Rc[i] - rc[d]) * ic;
                        float p1 = (R1[i] - r1[d]) * i1;
                        float v = pc - p1;
                        float vm1 = has2 ? (p1 - (R2[i] - r2[d]) * i2) : 0.0f;
                        val = v - vm1;
                    }
                } else if (k < 264) {
                    int a = k - 225, c = a / 3, d = a % 3;
                    int i0 = c_conn[c][0] * 3, i1j = c_conn[c][1] * 3;
                    float vx = (Rc[i1j]   - Rc[i0])   * ic;
                    float vy = (Rc[i1j+1] - Rc[i0+1]) * ic;
                    float vz = (Rc[i1j+2] - Rc[i0+2]) * ic;
                    float n = fmaxf(sqrtf(vx*vx + vy*vy + vz*vz), 1e-12f);
                    float comp = (d == 0 ? vx : (d == 1 ? vy : vz)) / n;
                    val = acosf(fminf(fmaxf(comp, -1.0f), 1.0f));
                }
                fv[u] = val;
            }
            uint32_t H, L;
            splitpack(fv[0], fv[1], H, L);
            *(uint32_t*)(rowH + k0 * 2) = H;
            *(uint32_t*)(rowL + k0 * 2) = L;
        }
    }
    __syncthreads();   // slab dead; ring slots may now be filled

    // ---- kick weight chunks 0 & 1 ----
    if (tid == 0) {
        MBAR_EXPECT(sb + MB_F0 + 0, W1CHB);
        bulk_g2s(sb + WBUF0, g_W1F, W1CHB, sb + MB_F0 + 0);
        MBAR_EXPECT(sb + MB_F0 + 8, W1CHB);
        bulk_g2s(sb + WBUF1, g_W1F + W1CHB, W1CHB, sb + MB_F0 + 8);
    }

    // ---- warp / lane geometry (8 warps: 2m x 4n) ----
    const int wm = wid >> 2;             // 0..1 -> m0 = wm*32
    const int wn = wid & 3;              // 0..3
    const int m0 = wm * 32;
    const int n0 = wn * 64;
    const int qr = lane >> 2;
    const int qk = (lane & 3) * 2;
    const int lrow = ((lane >> 3) & 1) * 8 + (lane & 7);
    const int lkof = (lane >> 4) * 8;

    // ======== GEMM1: hidden[64][256] = feat[64][272] @ W1c ========
    float acc[2][8][4];
    #pragma unroll
    for (int g = 0; g < 2; g++)
        #pragma unroll
        for (int nt = 0; nt < 8; nt++)
            #pragma unroll
            for (int q = 0; q < 4; q++) acc[g][nt][q] = 0.0f;

    for (int ck = 0; ck < CH1; ck++) {
        const int slot = ck & 1;
        const int ph   = (ck >> 1) & 1;
        const uint32_t wbase = slot ? (sb + WBUF1) : (sb + WBUF0);
        MBAR_WAIT(sb + MB_F0 + slot * 8, ph);

        uint32_t aH[2][4], aL[2][4];
        {
            uint32_t kb = (uint32_t)(ck * 16 + lkof) * 2;
            #pragma unroll
            for (int g = 0; g < 2; g++) {
                uint32_t r = (uint32_t)(m0 + g * 16 + lrow);
                ldm_x4(aH[g], sb + OFF_FH + r * FSB + kb);
                ldm_x4(aL[g], sb + OFF_FL + r * FSB + kb);
            }
        }
        const char* wb = (const char*)smem + (wbase - sb);
        #pragma unroll
        for (int nt = 0; nt < 8; nt++) {
            uint4 bv = *(const uint4*)(wb + ((wn * 8 + nt) * 32 + lane) * 16);
            mma16816(acc[0][nt], aH[0], bv.x, bv.y);
            mma16816(acc[1][nt], aH[1], bv.x, bv.y);
            mma16816(acc[0][nt], aH[0], bv.z, bv.w);
            mma16816(acc[1][nt], aH[1], bv.z, bv.w);
            mma16816(acc[0][nt], aL[0], bv.x, bv.y);
            mma16816(acc[1][nt], aL[1], bv.x, bv.y);
        }
        __syncthreads();                 // all warps done with this slot
        const int r = ck + 2;
        if (tid == 0 && r < NCHNK) {     // fire-and-forget refill
            MBAR_EXPECT(sb + MB_F0 + slot * 8, chunk_bytes(r));
            bulk_g2s(wbase, chunk_src(r), chunk_bytes(r), sb + MB_F0 + slot * 8);
        }
    }

    // ---- Epilogue 1: bias + relu + split -> hidden smem (overwrites feat) ----
    #pragma unroll
    for (int g = 0; g < 2; g++) {
        int r = m0 + g * 16 + qr;
        char* rH0 = smem + OFF_FH + (size_t)r * HSB;
        char* rL0 = smem + OFF_FL + (size_t)r * HSB;
        #pragma unroll
        for (int nt = 0; nt < 8; nt++) {
            int c = n0 + nt * 8 + qk;
            float bb0 = g_b1c[c], bb1 = g_b1c[c + 1];
            float h0 = fmaxf(acc[g][nt][0] + bb0, 0.0f);
            float h1 = fmaxf(acc[g][nt][1] + bb1, 0.0f);
            float h2 = fmaxf(acc[g][nt][2] + bb0, 0.0f);
            float h3 = fmaxf(acc[g][nt][3] + bb1, 0.0f);
            uint32_t H, L;
            splitpack(h0, h1, H, L);
            *(uint32_t*)(rH0 + c * 2) = H;
            *(uint32_t*)(rL0 + c * 2) = L;
            splitpack(h2, h3, H, L);
            *(uint32_t*)(rH0 + 8 * HSB + c * 2) = H;
            *(uint32_t*)(rL0 + 8 * HSB + c * 2) = L;
        }
    }
    __syncthreads();

    // ======== GEMM2: out[64][128] = hidden[64][256] @ W2 ========
    const int n02 = wn * 32;
    float acc2[2][4][4];
    #pragma unroll
    for (int g = 0; g < 2; g++)
        #pragma unroll
        for (int nt = 0; nt < 4; nt++)
            #pragma unroll
            for (int q = 0; q < 4; q++) acc2[g][nt][q] = 0.0f;

    for (int kt = 0; kt < CH2; kt++) {
        const int ck = CH1 + kt;
        const int slot = ck & 1;
        const int ph   = (ck >> 1) & 1;
        const uint32_t wbase = slot ? (sb + WBUF1) : (sb + WBUF0);
        MBAR_WAIT(sb + MB_F0 + slot * 8, ph);

        uint32_t aH[2][4], aL[2][4];
        {
            uint32_t kb = (uint32_t)(kt * 16 + lkof) * 2;
            #pragma unroll
            for (int g = 0; g < 2; g++) {
                uint32_t r = (uint32_t)(m0 + g * 16 + lrow);
                ldm_x4(aH[g], sb + OFF_FH + r * HSB + kb);
                ldm_x4(aL[g], sb + OFF_FL + r * HSB + kb);
            }
        }
        const char* wb = (const char*)smem + (wbase - sb);
        #pragma unroll
        for (int nt = 0; nt < 4; nt++) {
            uint4 bv = *(const uint4*)(wb + ((wn * 4 + nt) * 32 + lane) * 16);
            mma16816(acc2[0][nt], aH[0], bv.x, bv.y);
            mma16816(acc2[1][nt], aH[1], bv.x, bv.y);
            mma16816(acc2[0][nt], aH[0], bv.z, bv.w);
            mma16816(acc2[1][nt], aH[1], bv.z, bv.w);
            mma16816(acc2[0][nt], aL[0], bv.x, bv.y);
            mma16816(acc2[1][nt], aL[1], bv.x, bv.y);
        }
        __syncthreads();
        const int r = ck + 2;
        if (tid == 0 && r < NCHNK) {
            MBAR_EXPECT(sb + MB_F0 + slot * 8, chunk_bytes(r));
            bulk_g2s(wbase, chunk_src(r), chunk_bytes(r), sb + MB_F0 + slot * 8);
        }
    }

    // ---- Epilogue 2: + b2, store ----
    #pragma unroll
    for (int g = 0; g < 2; g++) {
        int r = m0 + g * 16 + qr;
        float* o0 = out + (size_t)(rowbase + r) * OUTD;
        float* o1 = out + (size_t)(rowbase + r + 8) * OUTD;
        #pragma unroll
        for (int nt = 0; nt < 4; nt++) {
            int c = n02 + nt * 8 + qk;
            float b20 = b2[c], b21 = b2[c + 1];
            float2 v0, v1;
            v0.x = acc2[g][nt][0] + b20; v0.y = acc2[g][nt][1] + b21;
            v1.x = acc2[g][nt][2] + b20; v1.y = acc2[g][nt][3] + b21;
            *reinterpret_cast<float2*>(o0 + c) = v0;
            *reinterpret_cast<float2*>(o1 + c) = v1;
        }
    }
}

// ---------------------------------------------------------------------------
extern "C" void kernel_launch(void* const* d_in, const int* in_sizes, int n_in,
                              void* d_out, int out_size) {
    const float* poses = (const float*)d_in[0];
    const float* W1    = (const float*)d_in[1];
    const float* b1    = (const float*)d_in[2];
    const float* gamma = (const float*)d_in[3];
    const float* beta  = (const float*)d_in[4];
    const float* rmean = (const float*)d_in[5];
    const float* rvar  = (const float*)d_in[6];
    const float* W2    = (const float*)d_in[7];
    const float* b2    = (const float*)d_in[8];
    const float* jw    = (const float*)d_in[9];
    float* out = (float*)d_out;

    cudaFuncSetAttribute(fused_kernel, cudaFuncAttributeMaxDynamicSharedMemorySize,
                         SMEM_TOTAL);

    prep_kernel<<<K1 + 256, 256>>>(W1, b1, gamma, beta, rmean, rvar, jw, W2);
    fused_kernel<<<(BBATCH * SSEQ) / TM, NTHR, SMEM_TOTAL>>>(poses, b2, out);
}

// round 16
// speedup vs baseline: 1.5521x; 1.1074x over previous
#include <cuda_runtime.h>
#include <cuda_bf16.h>
#include <math.h>
#include <stdint.h>
#include <stddef.h>

// Problem constants
#define BBATCH 64
#define SSEQ   2048
#define JJ     25
#define HID    256
#define OUTD   128
#define TM     128          // frames per CTA
#define NTHR   512
#define K1     272          // GEMM1 K (264 real + 8 pad)
#define CH1    17           // GEMM1 16-K chunks
#define CH2    16           // GEMM2 16-K chunks
#define NSLOT  17           // 9 W1 slots (8x32KB + 1x16KB) + 8 W2 slots (16KB)
#define PNS    77

// smem strides (bytes)
#define FSB 560             // feat row stride   -> banks 12 mod 32
#define HSB 528             // hidden row stride -> banks 4 mod 32

// smem layout (byte offsets)
#define MB_POSE 0
#define MB_F0   8                        // full[0]@8, full[1]@16
#define REG0    64                       // pose slab / weight slot 0 (32KB)
#define OFF_FH  (REG0 + 39040)           // 39104
#define OFF_FL  (OFF_FH + 71680)         // 110784
#define OFF_PN  (OFF_FL + 71680)         // 182464 (pn 40040B; weight slot 1 after stage 2)
#define SMEM_TOTAL (OFF_PN + 130 * PNS * 4)   // 222504

#define POSES_BYTES ((size_t)BBATCH * SSEQ * JJ * 3 * 4)

// Pre-fragmented folded weights (written by prep each launch)
// layout: [16-K chunk][n8 group][lane 32][16B = bH0,bH1,bL0,bL1]
__device__ __align__(16) unsigned char g_W1F[CH1 * 16384];   // 278528 B
__device__ __align__(16) unsigned char g_W2F[CH2 * 8192];    // 131072 B
__device__ float g_b1c[HID];

__constant__ int c_conn[13][2] = {
    {0,1},{1,5},{1,6},{5,7},{7,9},{6,8},{8,10},
    {1,11},{1,12},{11,13},{13,15},{12,14},{14,16}};

// ======================= helpers ==========================================
__device__ __forceinline__ uint32_t smem_u32(const void* p) {
    uint32_t a;
    asm("{ .reg .u64 t; cvta.to.shared.u64 t, %1; cvt.u32.u64 %0, t; }" : "=r"(a) : "l"(p));
    return a;
}
#define MBAR_INIT(mb, n) asm volatile("mbarrier.init.shared.b64 [%0], %1;" :: "r"(mb), "r"(n) : "memory")
#define MBAR_EXPECT(mb, bytes) asm volatile("mbarrier.arrive.expect_tx.shared.b64 _, [%0], %1;" :: "r"(mb), "r"(bytes) : "memory")
#define MBAR_WAIT(mb, par) do {                                              \
    uint32_t _mb = (mb), _p = (par), _d;                                     \
    asm volatile("{ .reg .pred p; mbarrier.try_wait.parity.acquire.cta.shared::cta.b64 p, [%1], %2; selp.b32 %0,1,0,p; }" \
        : "=r"(_d) : "r"(_mb), "r"(_p) : "memory");                          \
    if (!_d) {                                                               \
        asm volatile("{ .reg .pred P1; WL_%=: mbarrier.try_wait.parity.acquire.cta.shared::cta.b64 P1, [%0], %1, 0x989680;" \
            " @P1 bra.uni WD_%=; bra.uni WL_%=; WD_%=: }"                    \
            :: "r"(_mb), "r"(_p) : "memory");                                \
    } } while (0)

__device__ __forceinline__ void bulk_g2s(uint32_t dst, const void* gsrc, uint32_t bytes, uint32_t mb) {
    uint64_t g = (uint64_t)__cvta_generic_to_global(gsrc);
    asm volatile("cp.async.bulk.shared::cluster.global.mbarrier::complete_tx::bytes [%0], [%1], %2, [%3];"
        :: "r"(dst), "l"(g), "r"(bytes), "r"(mb) : "memory");
}

__device__ __forceinline__ void ldm_x4(uint32_t* r, uint32_t saddr) {
    asm volatile("ldmatrix.sync.aligned.m8n8.x4.shared.b16 {%0,%1,%2,%3}, [%4];"
        : "=r"(r[0]), "=r"(r[1]), "=r"(r[2]), "=r"(r[3]) : "r"(saddr));
}

// HMMA m16n8k16 row.col f32.bf16.bf16.f32, D accumulates in place.
__device__ __forceinline__ void mma16816(float* d, const uint32_t* a, uint32_t b0, uint32_t b1) {
    asm volatile(
        "mma.sync.aligned.m16n8k16.row.col.f32.bf16.bf16.f32 "
        "{%0,%1,%2,%3}, {%4,%5,%6,%7}, {%8,%9}, {%0,%1,%2,%3};"
        : "+f"(d[0]), "+f"(d[1]), "+f"(d[2]), "+f"(d[3])
        : "r"(a[0]), "r"(a[1]), "r"(a[2]), "r"(a[3]), "r"(b0), "r"(b1));
}

__device__ __forceinline__ void splitpack(float f0, float f1, uint32_t& hi, uint32_t& lo) {
    __nv_bfloat16 h0 = __float2bfloat16(f0);
    __nv_bfloat16 h1 = __float2bfloat16(f1);
    __nv_bfloat16 l0 = __float2bfloat16(f0 - __bfloat162float(h0));
    __nv_bfloat16 l1 = __float2bfloat16(f1 - __bfloat162float(h1));
    hi = (uint32_t)__bfloat16_as_ushort(h0) | ((uint32_t)__bfloat16_as_ushort(h1) << 16);
    lo = (uint32_t)__bfloat16_as_ushort(l0) | ((uint32_t)__bfloat16_as_ushort(l1) << 16);
}

// Unified slot stream: slots 0..8 = W1 (8x32KB + 16KB tail), 9..16 = W2 (16KB)
__device__ __forceinline__ const void* slot_src(int i) {
    return (i < 9) ? (const void*)(g_W1F + (size_t)i * 32768)
                   : (const void*)(g_W2F + (size_t)(i - 9) * 16384);
}
__device__ __forceinline__ uint32_t slot_bytes(int i) {
    return (i < 9) ? (i == 8 ? 16384u : 32768u) : 16384u;
}

// ======================= prep: fold + split + fragment weights =============
__global__ void prep_kernel(const float* __restrict__ W1, const float* __restrict__ b1,
                            const float* __restrict__ gamma, const float* __restrict__ beta,
                            const float* __restrict__ mean, const float* __restrict__ var,
                            const float* __restrict__ jw, const float* __restrict__ W2) {
    int t = threadIdx.x, blk = blockIdx.x;
    if (blk < K1) {
        int k = blk, h = t;          // t in [0,256)
        float g = gamma[h] * rsqrtf(var[h] + 1e-5f);
        float w = 0.0f;
        if (k < 264) {
            int korig, jidx;
            if (k < 225) { int sect = k / 75; int r = k % 75; jidx = r / 3; korig = jidx * 12 + sect * 3 + r % 3; }
            else         { int a = k - 225; jidx = a / 3; korig = jidx * 12 + 9 + a % 3; }
            w = W1[korig * HID + h] * g * jw[jidx];
        }
        __nv_bfloat16 hi = __float2bfloat16(w);
        __nv_bfloat16 lo = __float2bfloat16(w - __bfloat162float(hi));
        int chunk = k >> 4, kc = k & 15, n8 = h >> 3, qr = h & 7;
        int lane = qr * 4 + ((kc & 7) >> 1);
        int boff = (kc >> 3) * 4 + (kc & 1) * 2;
        size_t idx = (((size_t)chunk * 32 + n8) * 32 + lane) * 16 + boff;
        *(__nv_bfloat16*)(g_W1F + idx)     = hi;
        *(__nv_bfloat16*)(g_W1F + idx + 8) = lo;
        if (k == 0) g_b1c[h] = (b1[h] - mean[h]) * g + beta[h];
    } else if (t < 128) {
        int k = blk - K1, n = t;     // k in [0,256)
        float w = W2[k * OUTD + n];
        __nv_bfloat16 hi = __float2bfloat16(w);
        __nv_bfloat16 lo = __float2bfloat16(w - __bfloat162float(hi));
        int chunk = k >> 4, kc = k & 15, n8 = n >> 3, qr = n & 7;
        int lane = qr * 4 + ((kc & 7) >> 1);
        int boff = (kc >> 3) * 4 + (kc & 1) * 2;
        size_t idx = (((size_t)chunk * 16 + n8) * 32 + lane) * 16 + boff;
        *(__nv_bfloat16*)(g_W2F + idx)     = hi;
        *(__nv_bfloat16*)(g_W2F + idx + 8) = lo;
    }
}

// ======================= feature value ====================================
__device__ __forceinline__ float featval(int k, const float* P, const float* Pm1,
                                         const float* Pm2, bool has1, bool has2) {
    if (k < 75) return P[k];
    if (k < 150) { int i = k - 75; return has1 ? (P[i] - Pm1[i]) : 0.0f; }
    if (k < 225) {
        int i = k - 150;
        if (!has1) return 0.0f;
        float v = P[i] - Pm1[i];
        float vm1 = has2 ? (Pm1[i] - Pm2[i]) : 0.0f;
        return v - vm1;
    }
    if (k < 264) {
        int a = k - 225, c = a / 3, d = a % 3;
        int i0 = c_conn[c][0] * 3, i1 = c_conn[c][1] * 3;
        float vx = P[i1] - P[i0], vy = P[i1 + 1] - P[i0 + 1], vz = P[i1 + 2] - P[i0 + 2];
        float n = fmaxf(sqrtf(vx * vx + vy * vy + vz * vz), 1e-12f);
        float comp = (d == 0 ? vx : (d == 1 ? vy : vz)) / n;
        return acosf(fminf(fmaxf(comp, -1.0f), 1.0f));
    }
    return 0.0f;
}

// ======================= fused HMMA kernel =================================
__global__ void __launch_bounds__(NTHR, 1)
fused_kernel(const float* __restrict__ poses, const float* __restrict__ b2,
             float* __restrict__ out) {
    extern __shared__ char smem[];
    const uint32_t sb = smem_u32(smem);
    float* pn = (float*)(smem + OFF_PN);

    const int tid  = threadIdx.x;
    const int lane = tid & 31;
    const int wid  = tid >> 5;

    const int rowbase = blockIdx.x * TM;
    const int s0 = (blockIdx.x & 15) * TM;
    const int b  = blockIdx.x >> 4;

    // ---- init barriers + bulk-load pose slab into REG0 ----
    const int s_start = (s0 >= 2) ? (s0 - 2) : 0;
    const int nrows = 130 - (s0 == 0 ? 2 : 0);
    size_t base_bytes = ((size_t)b * SSEQ + s_start) * 300;
    size_t aligned = base_bytes & ~(size_t)15;
    const int delta = (int)(base_bytes - aligned);
    if (tid == 0) {
        MBAR_INIT(sb + MB_POSE, 1);
        MBAR_INIT(sb + MB_F0 + 0, 1);
        MBAR_INIT(sb + MB_F0 + 8, 1);
        size_t want = (size_t)((nrows * 300 + delta + 15) & ~15);
        size_t avail = POSES_BYTES - aligned;             // clamp: never read OOB
        uint32_t csz = (uint32_t)(want <= avail ? want : (avail & ~(size_t)15));
        MBAR_EXPECT(sb + MB_POSE, csz);
        bulk_g2s(sb + REG0, (const char*)poses + aligned, csz, sb + MB_POSE);
    }
    __syncthreads();
    MBAR_WAIT(sb + MB_POSE, 0);

    // ---- Stage 1: normalize 130 frames (128 + 2 halo) from smem slab ----
    if (tid < 130) {
        int s = s0 - 2 + tid;
        float* dst = pn + tid * PNS;
        if (s < 0) {
            for (int i = 0; i < 75; i++) dst[i] = 0.0f;
        } else {
            const float* src = (const float*)(smem + REG0) + (delta >> 2) + (s - s_start) * 75;
            float rx = src[0], ry = src[1], rz = src[2];
            float mx = 0.0f;
            for (int j = 0; j < JJ; j++) {
                float dx = src[j*3+0] - rx, dy = src[j*3+1] - ry, dz = src[j*3+2] - rz;
                dst[j*3+0] = dx; dst[j*3+1] = dy; dst[j*3+2] = dz;
                mx = fmaxf(mx, sqrtf(dx*dx + dy*dy + dz*dz));
            }
            float inv = 1.0f / (mx + 1e-8f);
            for (int i = 0; i < 75; i++) dst[i] *= inv;
        }
    }
    __syncthreads();   // raw slab dead; slot 0 (REG0) may be filled

    // ---- kick weight slot 0 (W1 chunks 0-1) — overlaps stage 2 ----
    if (tid == 0) {
        MBAR_EXPECT(sb + MB_F0 + 0, 32768);
        bulk_g2s(sb + REG0, g_W1F, 32768, sb + MB_F0 + 0);
    }

    // ---- Stage 2: features -> bf16 hi/lo smem planes ----
    {
        const int m  = tid >> 2;
        const int g4 = tid & 3;
        const float* P   = pn + (m + 2) * PNS;
        const float* Pm1 = pn + (m + 1) * PNS;
        const float* Pm2 = pn + (m + 0) * PNS;
        const bool has1 = (s0 + m) >= 1, has2 = (s0 + m) >= 2;
        char* rowH = smem + OFF_FH + (size_t)m * FSB;
        char* rowL = smem + OFF_FL + (size_t)m * FSB;
        for (int j = 0; j < 34; j++) {
            int k = g4 * 68 + 2 * j;
            float f0 = featval(k,     P, Pm1, Pm2, has1, has2);
            float f1 = featval(k + 1, P, Pm1, Pm2, has1, has2);
            uint32_t H, L;
            splitpack(f0, f1, H, L);
            *(uint32_t*)(rowH + k * 2) = H;
            *(uint32_t*)(rowL + k * 2) = L;
        }
    }
    __syncthreads();   // pn dead; slot 1 (OFF_PN) may be filled

    // ---- kick weight slot 1 (W1 chunks 2-3) ----
    if (tid == 0) {
        MBAR_EXPECT(sb + MB_F0 + 8, 32768);
        bulk_g2s(sb + OFF_PN, g_W1F + 32768, 32768, sb + MB_F0 + 8);
    }

    // ---- warp / lane geometry ----
    const int wm = wid >> 2;             // 0..3 -> m0 = wm*32
    const int wn = wid & 3;              // 0..3
    const int m0 = wm * 32;
    const int n0 = wn * 64;              // GEMM1 n-base
    const int qr = lane >> 2;
    const int qk = (lane & 3) * 2;
    const int lrow = ((lane >> 3) & 1) * 8 + (lane & 7);
    const int lkof = (lane >> 4) * 8;

    // hoisted base addresses
    const uint32_t aHb1 = sb + OFF_FH + (uint32_t)(m0 + lrow) * FSB + (uint32_t)lkof * 2;
    const uint32_t aLb1 = sb + OFF_FL + (uint32_t)(m0 + lrow) * FSB + (uint32_t)lkof * 2;
    const uint32_t bofs1 = (uint32_t)((wn * 8) * 32 + lane) * 16;   // GEMM1 B base in slot
    const uint32_t bofs2 = (uint32_t)((wn * 4) * 32 + lane) * 16;   // GEMM2 B base in slot

    // ======== GEMM1: hidden[128][256] = feat[128][272] @ W1c ========
    float acc[2][8][4];
    #pragma unroll
    for (int g = 0; g < 2; g++)
        #pragma unroll
        for (int nt = 0; nt < 8; nt++)
            #pragma unroll
            for (int q = 0; q < 4; q++) acc[g][nt][q] = 0.0f;

    for (int sl = 0; sl < 9; sl++) {
        const int buf = sl & 1;
        const int ph  = (sl >> 1) & 1;
        const uint32_t wbase = buf ? (sb + OFF_PN) : (sb + REG0);
        MBAR_WAIT(sb + MB_F0 + buf * 8, ph);

        const int nsub = (sl == 8) ? 1 : 2;
        for (int sub = 0; sub < nsub; sub++) {
            const int ck = sl * 2 + sub;
            uint32_t aH[2][4], aL[2][4];
            {
                uint32_t kb = (uint32_t)(ck * 16) * 2;
                ldm_x4(aH[0], aHb1 + kb);
                ldm_x4(aH[1], aHb1 + 16 * FSB + kb);
                ldm_x4(aL[0], aLb1 + kb);
                ldm_x4(aL[1], aLb1 + 16 * FSB + kb);
            }
            const char* wb = (const char*)smem + (wbase - sb) + sub * 16384 + bofs1;
            #pragma unroll
            for (int nt = 0; nt < 8; nt++) {
                uint4 bv = *(const uint4*)(wb + nt * 512);
                mma16816(acc[0][nt], aH[0], bv.x, bv.y);
                mma16816(acc[1][nt], aH[1], bv.x, bv.y);
                mma16816(acc[0][nt], aH[0], bv.z, bv.w);
                mma16816(acc[1][nt], aH[1], bv.z, bv.w);
                mma16816(acc[0][nt], aL[0], bv.x, bv.y);
                mma16816(acc[1][nt], aL[1], bv.x, bv.y);
            }
        }
        __syncthreads();                 // all reads of this slot done
        const int r = sl + 2;
        if (tid == 0 && r < NSLOT) {     // fire-and-forget refill
            MBAR_EXPECT(sb + MB_F0 + buf * 8, slot_bytes(r));
            bulk_g2s(wbase, slot_src(r), slot_bytes(r), sb + MB_F0 + buf * 8);
        }
    }
    __syncthreads();   // all GEMM1 feat reads done before hidden overwrite

    // ---- Epilogue 1: bias + relu + split -> hidden smem (overwrites feat) ----
    #pragma unroll
    for (int g = 0; g < 2; g++) {
        int r = m0 + g * 16 + qr;
        char* rH0 = smem + OFF_FH + (size_t)r * HSB;
        char* rL0 = smem + OFF_FL + (size_t)r * HSB;
        #pragma unroll
        for (int nt = 0; nt < 8; nt++) {
            int c = n0 + nt * 8 + qk;
            float bb0 = g_b1c[c], bb1 = g_b1c[c + 1];
            float h0 = fmaxf(acc[g][nt][0] + bb0, 0.0f);
            float h1 = fmaxf(acc[g][nt][1] + bb1, 0.0f);
            float h2 = fmaxf(acc[g][nt][2] + bb0, 0.0f);
            float h3 = fmaxf(acc[g][nt][3] + bb1, 0.0f);
            uint32_t H, L;
            splitpack(h0, h1, H, L);
            *(uint32_t*)(rH0 + c * 2) = H;
            *(uint32_t*)(rL0 + c * 2) = L;
            splitpack(h2, h3, H, L);
            *(uint32_t*)(rH0 + 8 * HSB + c * 2) = H;
            *(uint32_t*)(rL0 + 8 * HSB + c * 2) = L;
        }
    }
    __syncthreads();   // hidden visible to all warps

    // ======== GEMM2: out[128][128] = hidden[128][256] @ W2 ========
    const int n02 = wn * 32;
    const uint32_t aHb2 = sb + OFF_FH + (uint32_t)(m0 + lrow) * HSB + (uint32_t)lkof * 2;
    const uint32_t aLb2 = sb + OFF_FL + (uint32_t)(m0 + lrow) * HSB + (uint32_t)lkof * 2;
    float acc2[2][4][4];
    #pragma unroll
    for (int g = 0; g < 2; g++)
        #pragma unroll
        for (int nt = 0; nt < 4; nt++)
            #pragma unroll
            for (int q = 0; q < 4; q++) acc2[g][nt][q] = 0.0f;

    for (int sl = 9; sl < NSLOT; sl++) {
        const int buf = sl & 1;
        const int ph  = (sl >> 1) & 1;
        const uint32_t wbase = buf ? (sb + OFF_PN) : (sb + REG0);
        MBAR_WAIT(sb + MB_F0 + buf * 8, ph);

        for (int sub = 0; sub < 2; sub++) {
            const int kt = (sl - 9) * 2 + sub;
            uint32_t aH[2][4], aL[2][4];
            {
                uint32_t kb = (uint32_t)(kt * 16) * 2;
                ldm_x4(aH[0], aHb2 + kb);
                ldm_x4(aH[1], aHb2 + 16 * HSB + kb);
                ldm_x4(aL[0], aLb2 + kb);
                ldm_x4(aL[1], aLb2 + 16 * HSB + kb);
            }
            const char* wb = (const char*)smem + (wbase - sb) + sub * 8192 + bofs2;
            #pragma unroll
            for (int nt = 0; nt < 4; nt++) {
                uint4 bv = *(const uint4*)(wb + nt * 512);
                mma16816(acc2[0][nt], aH[0], bv.x, bv.y);
                mma16816(acc2[1][nt], aH[1], bv.x, bv.y);
                mma16816(acc2[0][nt], aH[0], bv.z, bv.w);
                mma16816(acc2[1][nt], aH[1], bv.z, bv.w);
                mma16816(acc2[0][nt], aL[0], bv.x, bv.y);
                mma16816(acc2[1][nt], aL[1], bv.x, bv.y);
            }
        }
        __syncthreads();
        const int r = sl + 2;
        if (tid == 0 && r < NSLOT) {
            MBAR_EXPECT(sb + MB_F0 + buf * 8, slot_bytes(r));
            bulk_g2s(wbase, slot_src(r), slot_bytes(r), sb + MB_F0 + buf * 8);
        }
    }

    // ---- Epilogue 2: + b2, store ----
    #pragma unroll
    for (int g = 0; g < 2; g++) {
        int r = m0 + g * 16 + qr;
        float* o0 = out + (size_t)(rowbase + r) * OUTD;
        float* o1 = out + (size_t)(rowbase + r + 8) * OUTD;
        #pragma unroll
        for (int nt = 0; nt < 4; nt++) {
            int c = n02 + nt * 8 + qk;
            float b20 = b2[c], b21 = b2[c + 1];
            float2 v0, v1;
            v0.x = acc2[g][nt][0] + b20; v0.y = acc2[g][nt][1] + b21;
            v1.x = acc2[g][nt][2] + b20; v1.y = acc2[g][nt][3] + b21;
            *reinterpret_cast<float2*>(o0 + c) = v0;
            *reinterpret_cast<float2*>(o1 + c) = v1;
        }
    }
}

// ---------------------------------------------------------------------------
extern "C" void kernel_launch(void* const* d_in, const int* in_sizes, int n_in,
                              void* d_out, int out_size) {
    const float* poses = (const float*)d_in[0];
    const float* W1    = (const float*)d_in[1];
    const float* b1    = (const float*)d_in[2];
    const float* gamma = (const float*)d_in[3];
    const float* beta  = (const float*)d_in[4];
    const float* rmean = (const float*)d_in[5];
    const float* rvar  = (const float*)d_in[6];
    const float* W2    = (const float*)d_in[7];
    const float* b2    = (const float*)d_in[8];
    const float* jw    = (const float*)d_in[9];
    float* out = (float*)d_out;

    cudaFuncSetAttribute(fused_kernel, cudaFuncAttributeMaxDynamicSharedMemorySize,
                         SMEM_TOTAL);

    prep_kernel<<<K1 + 256, 256>>>(W1, b1, gamma, beta, rmean, rvar, jw, W2);
    fused_kernel<<<(BBATCH * SSEQ) / TM, NTHR, SMEM_TOTAL>>>(poses, b2, out);
}

// round 17
// speedup vs baseline: 1.9560x; 1.2602x over previous
#include <cuda_runtime.h>
#include <cuda_bf16.h>
#include <math.h>
#include <stdint.h>
#include <stddef.h>

// Problem constants
#define BBATCH 64
#define SSEQ   2048
#define JJ     25
#define HID    256
#define OUTD   128
#define TM     128          // frames per CTA
#define NTHR   512
#define K1     272          // GEMM1 K (264 real + 8 pad)
#define CH1    17           // GEMM1 16-K chunks
#define CH2    16           // GEMM2 16-K chunks
#define NCH    33           // unified chunk stream
#define PNS    77

// smem strides (bytes)
#define FSB 560             // feat row stride   -> banks 12 mod 32
#define HSB 528             // hidden row stride -> banks 4 mod 32

#define W1CHB 16384
#define W2CHB 8192

// smem layout (byte offsets)
#define MB_POSE 0
#define MB_F0   8                        // full[0]@8, full[1]@16
#define WS0     64                       // weight slot 0 (16KB)
#define WS1     (64 + 16384)             // weight slot 1 (16KB)
#define OFF_PN  32832                    // pn: 130*77*4 = 40040
#define OFF_FH  72880                    // featH/hiddenH (raw pose slab lives here pre-stage2)
#define OFF_FL  (OFF_FH + 71680)         // 144560
#define SMEM_TOTAL (OFF_FL + 71680)      // 216240

#define POSES_BYTES ((size_t)BBATCH * SSEQ * JJ * 3 * 4)

// Pre-fragmented folded weights (written by prep each launch)
// layout: [16-K chunk][n8 group][lane 32][16B = bH0,bH1,bL0,bL1]
__device__ __align__(16) unsigned char g_W1F[CH1 * W1CHB];
__device__ __align__(16) unsigned char g_W2F[CH2 * W2CHB];
__device__ float g_b1c[HID];

__constant__ int c_conn[13][2] = {
    {0,1},{1,5},{1,6},{5,7},{7,9},{6,8},{8,10},
    {1,11},{1,12},{11,13},{13,15},{12,14},{14,16}};

// ======================= helpers ==========================================
__device__ __forceinline__ uint32_t smem_u32(const void* p) {
    uint32_t a;
    asm("{ .reg .u64 t; cvta.to.shared.u64 t, %1; cvt.u32.u64 %0, t; }" : "=r"(a) : "l"(p));
    return a;
}
#define MBAR_INIT(mb, n) asm volatile("mbarrier.init.shared.b64 [%0], %1;" :: "r"(mb), "r"(n) : "memory")
#define MBAR_EXPECT(mb, bytes) asm volatile("mbarrier.arrive.expect_tx.shared.b64 _, [%0], %1;" :: "r"(mb), "r"(bytes) : "memory")
#define MBAR_WAIT(mb, par) do {                                              \
    uint32_t _mb = (mb), _p = (par), _d;                                     \
    asm volatile("{ .reg .pred p; mbarrier.try_wait.parity.acquire.cta.shared::cta.b64 p, [%1], %2; selp.b32 %0,1,0,p; }" \
        : "=r"(_d) : "r"(_mb), "r"(_p) : "memory");                          \
    if (!_d) {                                                               \
        asm volatile("{ .reg .pred P1; WL_%=: mbarrier.try_wait.parity.acquire.cta.shared::cta.b64 P1, [%0], %1, 0x989680;" \
            " @P1 bra.uni WD_%=; bra.uni WL_%=; WD_%=: }"                    \
            :: "r"(_mb), "r"(_p) : "memory");                                \
    } } while (0)

__device__ __forceinline__ void bulk_g2s(uint32_t dst, const void* gsrc, uint32_t bytes, uint32_t mb) {
    uint64_t g = (uint64_t)__cvta_generic_to_global(gsrc);
    asm volatile("cp.async.bulk.shared::cluster.global.mbarrier::complete_tx::bytes [%0], [%1], %2, [%3];"
        :: "r"(dst), "l"(g), "r"(bytes), "r"(mb) : "memory");
}

__device__ __forceinline__ void ldm_x4(uint32_t* r, uint32_t saddr) {
    asm volatile("ldmatrix.sync.aligned.m8n8.x4.shared.b16 {%0,%1,%2,%3}, [%4];"
        : "=r"(r[0]), "=r"(r[1]), "=r"(r[2]), "=r"(r[3]) : "r"(saddr));
}

// HMMA m16n8k16 row.col f32.bf16.bf16.f32, D accumulates in place.
__device__ __forceinline__ void mma16816(float* d, const uint32_t* a, uint32_t b0, uint32_t b1) {
    asm volatile(
        "mma.sync.aligned.m16n8k16.row.col.f32.bf16.bf16.f32 "
        "{%0,%1,%2,%3}, {%4,%5,%6,%7}, {%8,%9}, {%0,%1,%2,%3};"
        : "+f"(d[0]), "+f"(d[1]), "+f"(d[2]), "+f"(d[3])
        : "r"(a[0]), "r"(a[1]), "r"(a[2]), "r"(a[3]), "r"(b0), "r"(b1));
}

__device__ __forceinline__ void splitpack(float f0, float f1, uint32_t& hi, uint32_t& lo) {
    __nv_bfloat16 h0 = __float2bfloat16(f0);
    __nv_bfloat16 h1 = __float2bfloat16(f1);
    __nv_bfloat16 l0 = __float2bfloat16(f0 - __bfloat162float(h0));
    __nv_bfloat16 l1 = __float2bfloat16(f1 - __bfloat162float(h1));
    hi = (uint32_t)__bfloat16_as_ushort(h0) | ((uint32_t)__bfloat16_as_ushort(h1) << 16);
    lo = (uint32_t)__bfloat16_as_ushort(l0) | ((uint32_t)__bfloat16_as_ushort(l1) << 16);
}

// Unified chunk stream: 0..16 = W1 (16KB), 17..32 = W2 (8KB)
__device__ __forceinline__ const void* chunk_src(int i) {
    return (i < CH1) ? (const void*)(g_W1F + (size_t)i * W1CHB)
                     : (const void*)(g_W2F + (size_t)(i - CH1) * W2CHB);
}
__device__ __forceinline__ uint32_t chunk_bytes(int i) {
    return (i < CH1) ? W1CHB : W2CHB;
}

// ======================= prep: fold + split + fragment weights =============
__global__ void prep_kernel(const float* __restrict__ W1, const float* __restrict__ b1,
                            const float* __restrict__ gamma, const float* __restrict__ beta,
                            const float* __restrict__ mean, const float* __restrict__ var,
                            const float* __restrict__ jw, const float* __restrict__ W2) {
    int t = threadIdx.x, blk = blockIdx.x;
    if (blk < K1) {
        int k = blk, h = t;          // t in [0,256)
        float g = gamma[h] * rsqrtf(var[h] + 1e-5f);
        float w = 0.0f;
        if (k < 264) {
            int korig, jidx;
            if (k < 225) { int sect = k / 75; int r = k % 75; jidx = r / 3; korig = jidx * 12 + sect * 3 + r % 3; }
            else         { int a = k - 225; jidx = a / 3; korig = jidx * 12 + 9 + a % 3; }
            w = W1[korig * HID + h] * g * jw[jidx];
        }
        __nv_bfloat16 hi = __float2bfloat16(w);
        __nv_bfloat16 lo = __float2bfloat16(w - __bfloat162float(hi));
        int chunk = k >> 4, kc = k & 15, n8 = h >> 3, qr = h & 7;
        int lane = qr * 4 + ((kc & 7) >> 1);
        int boff = (kc >> 3) * 4 + (kc & 1) * 2;
        size_t idx = (((size_t)chunk * 32 + n8) * 32 + lane) * 16 + boff;
        *(__nv_bfloat16*)(g_W1F + idx)     = hi;
        *(__nv_bfloat16*)(g_W1F + idx + 8) = lo;
        if (k == 0) g_b1c[h] = (b1[h] - mean[h]) * g + beta[h];
    } else if (t < 128) {
        int k = blk - K1, n = t;     // k in [0,256)
        float w = W2[k * OUTD + n];
        __nv_bfloat16 hi = __float2bfloat16(w);
        __nv_bfloat16 lo = __float2bfloat16(w - __bfloat162float(hi));
        int chunk = k >> 4, kc = k & 15, n8 = n >> 3, qr = n & 7;
        int lane = qr * 4 + ((kc & 7) >> 1);
        int boff = (kc >> 3) * 4 + (kc & 1) * 2;
        size_t idx = (((size_t)chunk * 16 + n8) * 32 + lane) * 16 + boff;
        *(__nv_bfloat16*)(g_W2F + idx)     = hi;
        *(__nv_bfloat16*)(g_W2F + idx + 8) = lo;
    }
}

// ======================= feature value ====================================
__device__ __forceinline__ float featval(int k, const float* P, const float* Pm1,
                                         const float* Pm2, bool has1, bool has2) {
    if (k < 75) return P[k];
    if (k < 150) { int i = k - 75; return has1 ? (P[i] - Pm1[i]) : 0.0f; }
    if (k < 225) {
        int i = k - 150;
        if (!has1) return 0.0f;
        float v = P[i] - Pm1[i];
        float vm1 = has2 ? (Pm1[i] - Pm2[i]) : 0.0f;
        return v - vm1;
    }
    if (k < 264) {
        int a = k - 225, c = a / 3, d = a % 3;
        int i0 = c_conn[c][0] * 3, i1 = c_conn[c][1] * 3;
        float vx = P[i1] - P[i0], vy = P[i1 + 1] - P[i0 + 1], vz = P[i1 + 2] - P[i0 + 2];
        float n = fmaxf(sqrtf(vx * vx + vy * vy + vz * vz), 1e-12f);
        float comp = (d == 0 ? vx : (d == 1 ? vy : vz)) / n;
        return acosf(fminf(fmaxf(comp, -1.0f), 1.0f));
    }
    return 0.0f;
}

// Produce features for one 16-K chunk: 128 frames x 8 pairs = 1024 tasks, 2/thread
__device__ __forceinline__ void make_feat(int fc, int tid, int s0,
                                          const float* pn, char* smemc) {
    #pragma unroll
    for (int t = 0; t < 2; t++) {
        int idx = t * NTHR + tid;
        int m = idx >> 3;
        int k = fc * 16 + (idx & 7) * 2;
        const float* P   = pn + (m + 2) * PNS;
        const float* Pm1 = pn + (m + 1) * PNS;
        const float* Pm2 = pn + (m + 0) * PNS;
        const bool has1 = (s0 + m) >= 1, has2 = (s0 + m) >= 2;
        float f0 = featval(k,     P, Pm1, Pm2, has1, has2);
        float f1 = featval(k + 1, P, Pm1, Pm2, has1, has2);
        uint32_t H, L;
        splitpack(f0, f1, H, L);
        *(uint32_t*)(smemc + OFF_FH + (size_t)m * FSB + k * 2) = H;
        *(uint32_t*)(smemc + OFF_FL + (size_t)m * FSB + k * 2) = L;
    }
}

// ======================= fused HMMA kernel =================================
__global__ void __launch_bounds__(NTHR, 1)
fused_kernel(const float* __restrict__ poses, const float* __restrict__ b2,
             float* __restrict__ out) {
    extern __shared__ char smem[];
    const uint32_t sb = smem_u32(smem);
    float* pn = (float*)(smem + OFF_PN);

    const int tid  = threadIdx.x;
    const int lane = tid & 31;
    const int wid  = tid >> 5;

    const int rowbase = blockIdx.x * TM;
    const int s0 = (blockIdx.x & 15) * TM;
    const int b  = blockIdx.x >> 4;

    // ---- init barriers; kick pose slab (into featH region) + W chunks 0,1 ----
    const int s_start = (s0 >= 2) ? (s0 - 2) : 0;
    const int nrows = 130 - (s0 == 0 ? 2 : 0);
    size_t base_bytes = ((size_t)b * SSEQ + s_start) * 300;
    size_t aligned = base_bytes & ~(size_t)15;
    const int delta = (int)(base_bytes - aligned);
    if (tid == 0) {
        MBAR_INIT(sb + MB_POSE, 1);
        MBAR_INIT(sb + MB_F0 + 0, 1);
        MBAR_INIT(sb + MB_F0 + 8, 1);
        size_t want = (size_t)((nrows * 300 + delta + 15) & ~15);
        size_t avail = POSES_BYTES - aligned;             // clamp: never read OOB
        uint32_t csz = (uint32_t)(want <= avail ? want : (avail & ~(size_t)15));
        MBAR_EXPECT(sb + MB_POSE, csz);
        bulk_g2s(sb + OFF_FH, (const char*)poses + aligned, csz, sb + MB_POSE);
        MBAR_EXPECT(sb + MB_F0 + 0, W1CHB);
        bulk_g2s(sb + WS0, g_W1F, W1CHB, sb + MB_F0 + 0);
        MBAR_EXPECT(sb + MB_F0 + 8, W1CHB);
        bulk_g2s(sb + WS1, g_W1F + W1CHB, W1CHB, sb + MB_F0 + 8);
    }
    __syncthreads();
    MBAR_WAIT(sb + MB_POSE, 0);

    // ---- Stage 1: normalize 130 frames (slab lives in featH region) ----
    if (tid < 130) {
        int s = s0 - 2 + tid;
        float* dst = pn + tid * PNS;
        if (s < 0) {
            for (int i = 0; i < 75; i++) dst[i] = 0.0f;
        } else {
            const float* src = (const float*)(smem + OFF_FH) + (delta >> 2) + (s - s_start) * 75;
            float rx = src[0], ry = src[1], rz = src[2];
            float mx = 0.0f;
            for (int j = 0; j < JJ; j++) {
                float dx = src[j*3+0] - rx, dy = src[j*3+1] - ry, dz = src[j*3+2] - rz;
                dst[j*3+0] = dx; dst[j*3+1] = dy; dst[j*3+2] = dz;
                mx = fmaxf(mx, sqrtf(dx*dx + dy*dy + dz*dz));
            }
            float inv = 1.0f / (mx + 1e-8f);
            for (int i = 0; i < 75; i++) dst[i] *= inv;
        }
    }
    __syncthreads();   // slab dead; featH/featL writable; barrier inits visible

    // ---- features for chunks 0..3 upfront ----
    for (int fc = 0; fc < 4; fc++)
        make_feat(fc, tid, s0, pn, smem);
    __syncthreads();

    // ---- warp / lane geometry ----
    const int wm = wid >> 2;             // 0..3 -> m0 = wm*32
    const int wn = wid & 3;              // 0..3
    const int m0 = wm * 32;
    const int n0 = wn * 64;              // GEMM1 n-base
    const int qr = lane >> 2;
    const int qk = (lane & 3) * 2;
    const int lrow = ((lane >> 3) & 1) * 8 + (lane & 7);
    const int lkof = (lane >> 4) * 8;

    const uint32_t aHb1 = sb + OFF_FH + (uint32_t)(m0 + lrow) * FSB + (uint32_t)lkof * 2;
    const uint32_t aLb1 = sb + OFF_FL + (uint32_t)(m0 + lrow) * FSB + (uint32_t)lkof * 2;
    const uint32_t bofs1 = (uint32_t)((wn * 8) * 32 + lane) * 16;
    const uint32_t bofs2 = (uint32_t)((wn * 4) * 32 + lane) * 16;

    // ======== GEMM1: hidden[128][256] = feat[128][272] @ W1c ========
    float acc[2][8][4];
    #pragma unroll
    for (int g = 0; g < 2; g++)
        #pragma unroll
        for (int nt = 0; nt < 8; nt++)
            #pragma unroll
            for (int q = 0; q < 4; q++) acc[g][nt][q] = 0.0f;

    for (int ck = 0; ck < CH1; ck++) {
        const int buf = ck & 1;
        const int ph  = (ck >> 1) & 1;
        const uint32_t wbase = buf ? (sb + WS1) : (sb + WS0);
        MBAR_WAIT(sb + MB_F0 + buf * 8, ph);

        uint32_t aH[2][4], aL[2][4];
        {
            uint32_t kb = (uint32_t)ck * 32;
            ldm_x4(aH[0], aHb1 + kb);
            ldm_x4(aH[1], aHb1 + 16 * FSB + kb);
            ldm_x4(aL[0], aLb1 + kb);
            ldm_x4(aL[1], aLb1 + 16 * FSB + kb);
        }
        const char* wb = (const char*)smem + (wbase - sb) + bofs1;
        #pragma unroll
        for (int nt = 0; nt < 8; nt++) {
            uint4 bv = *(const uint4*)(wb + nt * 512);
            mma16816(acc[0][nt], aH[0], bv.x, bv.y);
            mma16816(acc[1][nt], aH[1], bv.x, bv.y);
            mma16816(acc[0][nt], aH[0], bv.z, bv.w);
            mma16816(acc[1][nt], aH[1], bv.z, bv.w);
            mma16816(acc[0][nt], aL[0], bv.x, bv.y);
            mma16816(acc[1][nt], aL[1], bv.x, bv.y);
        }
        // produce features for chunk ck+4 under the MMA shadow
        const int fc = ck + 4;
        if (fc < CH1) make_feat(fc, tid, s0, pn, smem);

        __syncthreads();
        const int r = ck + 2;
        if (tid == 0 && r < NCH) {
            MBAR_EXPECT(sb + MB_F0 + buf * 8, chunk_bytes(r));
            bulk_g2s(wbase, chunk_src(r), chunk_bytes(r), sb + MB_F0 + buf * 8);
        }
    }

    // ---- Epilogue 1: bias + relu + split -> hidden smem (overwrites feat) ----
    #pragma unroll
    for (int g = 0; g < 2; g++) {
        int r = m0 + g * 16 + qr;
        char* rH0 = smem + OFF_FH + (size_t)r * HSB;
        char* rL0 = smem + OFF_FL + (size_t)r * HSB;
        #pragma unroll
        for (int nt = 0; nt < 8; nt++) {
            int c = n0 + nt * 8 + qk;
            float bb0 = g_b1c[c], bb1 = g_b1c[c + 1];
            float h0 = fmaxf(acc[g][nt][0] + bb0, 0.0f);
            float h1 = fmaxf(acc[g][nt][1] + bb1, 0.0f);
            float h2 = fmaxf(acc[g][nt][2] + bb0, 0.0f);
            float h3 = fmaxf(acc[g][nt][3] + bb1, 0.0f);
            uint32_t H, L;
            splitpack(h0, h1, H, L);
            *(uint32_t*)(rH0 + c * 2) = H;
            *(uint32_t*)(rL0 + c * 2) = L;
            splitpack(h2, h3, H, L);
            *(uint32_t*)(rH0 + 8 * HSB + c * 2) = H;
            *(uint32_t*)(rL0 + 8 * HSB + c * 2) = L;
        }
    }
    __syncthreads();

    // ======== GEMM2: out[128][128] = hidden[128][256] @ W2 ========
    const int n02 = wn * 32;
    const uint32_t aHb2 = sb + OFF_FH + (uint32_t)(m0 + lrow) * HSB + (uint32_t)lkof * 2;
    const uint32_t aLb2 = sb + OFF_FL + (uint32_t)(m0 + lrow) * HSB + (uint32_t)lkof * 2;
    float acc2[2][4][4];
    #pragma unroll
    for (int g = 0; g < 2; g++)
        #pragma unroll
        for (int nt = 0; nt < 4; nt++)
            #pragma unroll
            for (int q = 0; q < 4; q++) acc2[g][nt][q] = 0.0f;

    for (int ck = CH1; ck < NCH; ck++) {
        const int kt = ck - CH1;
        const int buf = ck & 1;
        const int ph  = (ck >> 1) & 1;
        const uint32_t wbase = buf ? (sb + WS1) : (sb + WS0);
        MBAR_WAIT(sb + MB_F0 + buf * 8, ph);

        uint32_t aH[2][4], aL[2][4];
        {
            uint32_t kb = (uint32_t)kt * 32;
            ldm_x4(aH[0], aHb2 + kb);
            ldm_x4(aH[1], aHb2 + 16 * HSB + kb);
            ldm_x4(aL[0], aLb2 + kb);
            ldm_x4(aL[1], aLb2 + 16 * HSB + kb);
        }
        const char* wb = (const char*)smem + (wbase - sb) + bofs2;
        #pragma unroll
        for (int nt = 0; nt < 4; nt++) {
            uint4 bv = *(const uint4*)(wb + nt * 512);
            mma16816(acc2[0][nt], aH[0], bv.x, bv.y);
            mma16816(acc2[1][nt], aH[1], bv.x, bv.y);
            mma16816(acc2[0][nt], aH[0], bv.z, bv.w);
            mma16816(acc2[1][nt], aH[1], bv.z, bv.w);
            mma16816(acc2[0][nt], aL[0], bv.x, bv.y);
            mma16816(acc2[1][nt], aL[1], bv.x, bv.y);
        }
        __syncthreads();
        const int r = ck + 2;
        if (tid == 0 && r < NCH) {
            MBAR_EXPECT(sb + MB_F0 + buf * 8, chunk_bytes(r));
            bulk_g2s(wbase, chunk_src(r), chunk_bytes(r), sb + MB_F0 + buf * 8);
        }
    }

    // ---- Epilogue 2: + b2, store ----
    #pragma unroll
    for (int g = 0; g < 2; g++) {
        int r = m0 + g * 16 + qr;
        float* o0 = out + (size_t)(rowbase + r) * OUTD;
        float* o1 = out + (size_t)(rowbase + r + 8) * OUTD;
        #pragma unroll
        for (int nt = 0; nt < 4; nt++) {
            int c = n02 + nt * 8 + qk;
            float b20 = b2[c], b21 = b2[c + 1];
            float2 v0, v1;
            v0.x = acc2[g][nt][0] + b20; v0.y = acc2[g][nt][1] + b21;
            v1.x = acc2[g][nt][2] + b20; v1.y = acc2[g][nt][3] + b21;
            *reinterpret_cast<float2*>(o0 + c) = v0;
            *reinterpret_cast<float2*>(o1 + c) = v1;
        }
    }
}

// ---------------------------------------------------------------------------
extern "C" void kernel_launch(void* const* d_in, const int* in_sizes, int n_in,
                              void* d_out, int out_size) {
    const float* poses = (const float*)d_in[0];
    const float* W1    = (const float*)d_in[1];
    const float* b1    = (const float*)d_in[2];
    const float* gamma = (const float*)d_in[3];
    const float* beta  = (const float*)d_in[4];
    const float* rmean = (const float*)d_in[5];
    const float* rvar  = (const float*)d_in[6];
    const float* W2    = (const float*)d_in[7];
    const float* b2    = (const float*)d_in[8];
    const float* jw    = (const float*)d_in[9];
    float* out = (float*)d_out;

    cudaFuncSetAttribute(fused_kernel, cudaFuncAttributeMaxDynamicSharedMemorySize,
                         SMEM_TOTAL);

    prep_kernel<<<K1 + 256, 256>>>(W1, b1, gamma, beta, rmean, rvar, jw, W2);
    fused_kernel<<<(BBATCH * SSEQ) / TM, NTHR, SMEM_TOTAL>>>(poses, b2, out);
}